// round 14
// baseline (speedup 1.0000x reference)
#include <cuda_runtime.h>
#include <math.h>

#define D 128
#define TILE_E 64
#define PERSIST 304

// ---------------- device scratch (no allocation allowed) ----------------
__device__ float g_h0[640000 * 128];
__device__ float g_Pa[640000 * 128];
__device__ float g_Pb[640000 * 128];
__device__ float g_SA[50048 * 128];
__device__ float g_SB[50048 * 128];
__device__ float g_mnode[50048 * 128];
__device__ float g_nodeW[50048 * 128];
__device__ float g_graph[256 * 128];

__device__ __forceinline__ float lrelu(float x) { return x >= 0.f ? x : 0.01f * x; }

__device__ __forceinline__ unsigned long long ffma2(unsigned long long a,
                                                    unsigned long long b,
                                                    unsigned long long c) {
    unsigned long long d;
    asm("fma.rn.f32x2 %0, %1, %2, %3;" : "=l"(d) : "l"(a), "l"(b), "l"(c));
    return d;
}
__device__ __forceinline__ unsigned long long dup2(float x) {
    unsigned long long d;
    asm("mov.b64 %0, {%1, %1};" : "=l"(d) : "f"(x));
    return d;
}

// ~5000-cycle dependent-FFMA2 spin to desynchronize co-resident CTAs.
__device__ __forceinline__ void desync_spin() {
    unsigned long long x = dup2(1.0e-30f);
    unsigned long long y = dup2(0.999999f);
#pragma unroll 1
    for (int i = 0; i < 1250; i++) x = ffma2(x, y, x);
    // never true; keeps the chain alive
    if (__uint_as_float((unsigned int)x) > 1.0e30f) ((volatile float*)g_graph)[0] = 1.f;
}

// 64x128 tile GEMM: As [64][128] row-major, Ws [128][128] row-major (k-major)
__device__ __forceinline__ void gemm_tile(const float* __restrict__ As,
                                          const float* __restrict__ Ws,
                                          unsigned long long acc[4][4],
                                          int tx, int ty) {
    const float4* As4 = (const float4*)As;
    const int r0 = ty * 4;
#pragma unroll 2
    for (int k = 0; k < D; k += 4) {
        float4 a0 = As4[(r0 + 0) * 32 + (k >> 2)];
        float4 a1 = As4[(r0 + 1) * 32 + (k >> 2)];
        float4 a2 = As4[(r0 + 2) * 32 + (k >> 2)];
        float4 a3 = As4[(r0 + 3) * 32 + (k >> 2)];
        float v0[4] = {a0.x, a0.y, a0.z, a0.w};
        float v1[4] = {a1.x, a1.y, a1.z, a1.w};
        float v2[4] = {a2.x, a2.y, a2.z, a2.w};
        float v3[4] = {a3.x, a3.y, a3.z, a3.w};
#pragma unroll
        for (int kk = 0; kk < 4; kk++) {
            ulonglong2 b0 = *(const ulonglong2*)(Ws + (k + kk) * D + tx * 4);
            ulonglong2 b1 = *(const ulonglong2*)(Ws + (k + kk) * D + 64 + tx * 4);
            unsigned long long d0 = dup2(v0[kk]);
            unsigned long long d1 = dup2(v1[kk]);
            unsigned long long d2 = dup2(v2[kk]);
            unsigned long long d3 = dup2(v3[kk]);
            acc[0][0] = ffma2(d0, b0.x, acc[0][0]); acc[0][1] = ffma2(d0, b0.y, acc[0][1]);
            acc[0][2] = ffma2(d0, b1.x, acc[0][2]); acc[0][3] = ffma2(d0, b1.y, acc[0][3]);
            acc[1][0] = ffma2(d1, b0.x, acc[1][0]); acc[1][1] = ffma2(d1, b0.y, acc[1][1]);
            acc[1][2] = ffma2(d1, b1.x, acc[1][2]); acc[1][3] = ffma2(d1, b1.y, acc[1][3]);
            acc[2][0] = ffma2(d2, b0.x, acc[2][0]); acc[2][1] = ffma2(d2, b0.y, acc[2][1]);
            acc[2][2] = ffma2(d2, b1.x, acc[2][2]); acc[2][3] = ffma2(d2, b1.y, acc[2][3]);
            acc[3][0] = ffma2(d3, b0.x, acc[3][0]); acc[3][1] = ffma2(d3, b0.y, acc[3][1]);
            acc[3][2] = ffma2(d3, b1.x, acc[3][2]); acc[3][3] = ffma2(d3, b1.y, acc[3][3]);
        }
    }
}

__device__ __forceinline__ void writeback_tile(float* __restrict__ Pnew,
                                               float* __restrict__ Snew,
                                               const int* __restrict__ sdst,
                                               unsigned long long acc[4][4],
                                               int e0, int E, int tx, int ty) {
    union U { unsigned long long u; float2 f; };
#pragma unroll
    for (int i = 0; i < 4; i++) {
        int el = ty * 4 + i;
        int e = e0 + el;
        if (e < E) {
            U u0, u1, u2, u3;
            u0.u = acc[i][0]; u1.u = acc[i][1]; u2.u = acc[i][2]; u3.u = acc[i][3];
            float4 w0 = make_float4(u0.f.x, u0.f.y, u1.f.x, u1.f.y);
            float4 w1 = make_float4(u2.f.x, u2.f.y, u3.f.x, u3.f.y);
            ((float4*)Pnew)[e * 32 + tx] = w0;
            ((float4*)Pnew)[e * 32 + 16 + tx] = w1;
            int dn = sdst[el];
            float* sp = Snew + dn * D + tx * 4;
            atomicAdd(sp + 0, w0.x); atomicAdd(sp + 1, w0.y);
            atomicAdd(sp + 2, w0.z); atomicAdd(sp + 3, w0.w);
            float* sq = Snew + dn * D + 64 + tx * 4;
            atomicAdd(sq + 0, w1.x); atomicAdd(sq + 1, w1.y);
            atomicAdd(sq + 2, w1.z); atomicAdd(sq + 3, w1.w);
        }
    }
}

// ---------------- zero ----------------
__global__ void k_zero(float4* p, int n4) {
    int i = blockIdx.x * blockDim.x + threadIdx.x;
    if (i < n4) p[i] = make_float4(0.f, 0.f, 0.f, 0.f);
}

// ---------------- nodeW = node_feat @ W_edge[0:64,:] ----------------
__global__ void k_nodeW(const float* __restrict__ nf, const float* __restrict__ We,
                        float* __restrict__ nodeW, int N) {
    __shared__ float s[16 * 64];
    int n0 = blockIdx.x * 16;
    int j = threadIdx.x;
    for (int f = j; f < 16 * 64; f += 128) {
        int r = f >> 6, i = f & 63;
        int n = n0 + r;
        s[f] = (n < N) ? nf[n * 64 + i] : 0.f;
    }
    __syncthreads();
    float acc[16];
#pragma unroll
    for (int r = 0; r < 16; r++) acc[r] = 0.f;
    for (int i = 0; i < 64; i++) {
        float w = We[i * D + j];
#pragma unroll
        for (int r = 0; r < 16; r++) acc[r] += s[r * 64 + i] * w;
    }
#pragma unroll
    for (int r = 0; r < 16; r++) {
        int n = n0 + r;
        if (n < N) nodeW[n * D + j] = acc[r];
    }
}

// ---------------- round 0: h0 build + P0 = h0@W + scatter S0 ----------------
__global__ void __launch_bounds__(256, 2) k_round0(
    const float* __restrict__ edge_feat, const float* __restrict__ We,
    const float* __restrict__ W_upd, const float* __restrict__ nodeW,
    const int* __restrict__ src, const int* __restrict__ dst,
    float* __restrict__ h0, float* __restrict__ Pnew, float* __restrict__ Snew, int E) {
    extern __shared__ float sm[];
    float* As  = sm;
    float* Ws  = sm + 8192;
    float* Web = sm + 24576;
    float* sef = sm + 26624;
    int* ssrc  = (int*)(sm + 27648);
    int* sdst  = ssrc + TILE_E;
    int tid = threadIdx.x;
    int tx = tid & 15, ty = tid >> 4;

    for (int i = tid; i < D * D; i += 256) Ws[i] = W_upd[i];
    for (int i = tid; i < 16 * D; i += 256) Web[i] = We[64 * D + i];
    if (blockIdx.x >= (gridDim.x >> 1)) desync_spin();

    int numTiles = (E + TILE_E - 1) / TILE_E;
    for (int t = blockIdx.x; t < numTiles; t += gridDim.x) {
        int e0 = t * TILE_E;
        __syncthreads();
        if (tid < TILE_E) {
            int e = e0 + tid;
            ssrc[tid] = (e < E) ? src[e] : 0;
            sdst[tid] = (e < E) ? dst[e] : 0;
        }
        for (int f = tid; f < TILE_E * 16; f += 256) {
            int e = e0 + (f >> 4);
            sef[f] = (e < E) ? edge_feat[e0 * 16 + f] : 0.f;
        }
        __syncthreads();
#pragma unroll
        for (int it = 0; it < 8; it++) {
            int flat = it * 256 + tid;
            int el = flat >> 5, k4 = flat & 31;
            int e = e0 + el;
            float4 v = make_float4(0.f, 0.f, 0.f, 0.f);
            if (e < E) {
                v = ((const float4*)nodeW)[ssrc[el] * 32 + k4];
#pragma unroll
                for (int i = 0; i < 16; i++) {
                    float f = sef[el * 16 + i];
                    float4 w = ((const float4*)Web)[i * 32 + k4];
                    v.x += f * w.x; v.y += f * w.y; v.z += f * w.z; v.w += f * w.w;
                }
                v.x = lrelu(v.x); v.y = lrelu(v.y); v.z = lrelu(v.z); v.w = lrelu(v.w);
                ((float4*)h0)[e * 32 + k4] = v;
            }
            ((float4*)As)[flat] = v;
        }
        __syncthreads();
        unsigned long long acc[4][4];
#pragma unroll
        for (int i = 0; i < 4; i++)
#pragma unroll
            for (int jj = 0; jj < 4; jj++) acc[i][jj] = 0ULL;
        gemm_tile(As, Ws, acc, tx, ty);
        writeback_tile(Pnew, Snew, sdst, acc, e0, E, tx, ty);
    }
}

// ---------------- rounds 1..3: build h on the fly, P=h@W, scatter S ----------------
__global__ void __launch_bounds__(256, 2) k_round(
    const float* __restrict__ Sprev, const float* __restrict__ Pprev,
    const float* __restrict__ h0, const float* __restrict__ W_upd,
    const int* __restrict__ src, const int* __restrict__ dst, const int* __restrict__ rev,
    float* __restrict__ Pnew, float* __restrict__ Snew, int E) {
    extern __shared__ float sm[];
    float* As = sm;
    float* Ws = sm + 8192;
    int* ssrc = (int*)(sm + 24576);
    int* sdst = ssrc + TILE_E;
    int* srev = sdst + TILE_E;
    int tid = threadIdx.x;
    int tx = tid & 15, ty = tid >> 4;

    for (int i = tid; i < D * D; i += 256) Ws[i] = W_upd[i];
    if (blockIdx.x >= (gridDim.x >> 1)) desync_spin();

    int numTiles = (E + TILE_E - 1) / TILE_E;
    for (int t = blockIdx.x; t < numTiles; t += gridDim.x) {
        int e0 = t * TILE_E;
        __syncthreads();
        if (tid < TILE_E) {
            int e = e0 + tid;
            ssrc[tid] = (e < E) ? src[e] : 0;
            sdst[tid] = (e < E) ? dst[e] : 0;
            srev[tid] = (e < E) ? rev[e] : 0;
        }
        __syncthreads();
#pragma unroll
        for (int it = 0; it < 8; it++) {
            int flat = it * 256 + tid;
            int el = flat >> 5, k4 = flat & 31;
            int e = e0 + el;
            float4 v = make_float4(0.f, 0.f, 0.f, 0.f);
            if (e < E) {
                float4 s4 = ((const float4*)Sprev)[ssrc[el] * 32 + k4];
                float4 p4 = ((const float4*)Pprev)[srev[el] * 32 + k4];
                float4 z4 = ((const float4*)h0)[e * 32 + k4];
                v.x = lrelu(s4.x - p4.x + z4.x);
                v.y = lrelu(s4.y - p4.y + z4.y);
                v.z = lrelu(s4.z - p4.z + z4.z);
                v.w = lrelu(s4.w - p4.w + z4.w);
            }
            ((float4*)As)[flat] = v;
        }
        __syncthreads();
        unsigned long long acc[4][4];
#pragma unroll
        for (int i = 0; i < 4; i++)
#pragma unroll
            for (int jj = 0; jj < 4; jj++) acc[i][jj] = 0ULL;
        gemm_tile(As, Ws, acc, tx, ty);
        writeback_tile(Pnew, Snew, sdst, acc, e0, E, tx, ty);
    }
}

// ---------------- final: h4 build + scatter to m_node ----------------
__global__ void k_final(const float* __restrict__ Sprev, const float* __restrict__ Pprev,
                        const float* __restrict__ h0,
                        const int* __restrict__ src, const int* __restrict__ dst,
                        const int* __restrict__ rev, float* __restrict__ mnode, int E) {
    int idx = blockIdx.x * blockDim.x + threadIdx.x;
    if (idx >= E * 32) return;
    int e = idx >> 5, k4 = idx & 31;
    int sn = src[e], re = rev[e], dn = dst[e];
    float4 s4 = ((const float4*)Sprev)[sn * 32 + k4];
    float4 p4 = ((const float4*)Pprev)[re * 32 + k4];
    float4 z4 = ((const float4*)h0)[e * 32 + k4];
    float4 v;
    v.x = lrelu(s4.x - p4.x + z4.x);
    v.y = lrelu(s4.y - p4.y + z4.y);
    v.z = lrelu(s4.z - p4.z + z4.z);
    v.w = lrelu(s4.w - p4.w + z4.w);
    float* mp = mnode + dn * D + k4 * 4;
    atomicAdd(mp + 0, v.x); atomicAdd(mp + 1, v.y);
    atomicAdd(mp + 2, v.z); atomicAdd(mp + 3, v.w);
}

// ---------------- node MLP + graph readout ----------------
__global__ void __launch_bounds__(128, 2) k_node(
    const float* __restrict__ nf, const float* __restrict__ mnode,
    const float* __restrict__ Wn, const float* __restrict__ bn,
    const int* __restrict__ gid, float* __restrict__ graph, int N) {
    extern __shared__ float sm[];
    float* Wns = sm;            // 192*128
    float* xc  = sm + 24576;    // 16*192
    int tid = threadIdx.x;
    for (int i = tid; i < 192 * 128; i += 128) Wns[i] = Wn[i];
    float bj = bn[tid];
    int numTiles = (N + 15) / 16;
    for (int t = blockIdx.x; t < numTiles; t += gridDim.x) {
        int n0 = t * 16;
        __syncthreads();
        for (int f = tid; f < 16 * 64; f += 128) {
            int r = f >> 6, i = f & 63; int n = n0 + r;
            xc[r * 192 + i] = (n < N) ? nf[n * 64 + i] : 0.f;
        }
        for (int f = tid; f < 16 * 128; f += 128) {
            int r = f >> 7, i = f & 127; int n = n0 + r;
            xc[r * 192 + 64 + i] = (n < N) ? mnode[n * 128 + i] : 0.f;
        }
        __syncthreads();
        for (int r = 0; r < 16; r++) {
            int n = n0 + r;
            if (n >= N) break;
            float acc = bj;
#pragma unroll 8
            for (int i = 0; i < 192; i++) acc += xc[r * 192 + i] * Wns[i * 128 + tid];
            atomicAdd(&graph[gid[n] * 128 + tid], lrelu(acc));
        }
    }
}

// ---------------- MoE head: 4 graphs per block ----------------
__global__ void k_moe(const float* __restrict__ graph, const float* __restrict__ extra,
                      const float* __restrict__ Wg1, const float* __restrict__ bg1,
                      const float* __restrict__ Wg2, const float* __restrict__ bg2,
                      const float* __restrict__ Wg3, const float* __restrict__ bg3,
                      const float* __restrict__ EW1, const float* __restrict__ Eb1,
                      const float* __restrict__ EW2, const float* __restrict__ Eb2,
                      const float* __restrict__ EW3, const float* __restrict__ Eb3,
                      float* __restrict__ out, int B) {
    __shared__ float sx[4][144];
    __shared__ float sh[4][128];
    __shared__ float sh2[4][128];
    __shared__ float slog[4][8];
    __shared__ float sev[4][8];
    __shared__ float red[4][4];
    int j = threadIdx.x;
    int b0 = blockIdx.x * 4;
    for (int g = 0; g < 4; g++) {
        int b = b0 + g;
        if (b < B) {
            sx[g][j] = graph[b * 128 + j];
            if (j < 16) sx[g][128 + j] = extra[b * 16 + j];
        } else {
            sx[g][j] = 0.f;
            if (j < 16) sx[g][128 + j] = 0.f;
        }
    }
    __syncthreads();
    float acc[4];
#pragma unroll
    for (int g = 0; g < 4; g++) acc[g] = bg1[j];
    for (int i = 0; i < 144; i++) {
        float w = Wg1[i * 128 + j];
#pragma unroll
        for (int g = 0; g < 4; g++) acc[g] += sx[g][i] * w;
    }
#pragma unroll
    for (int g = 0; g < 4; g++) sh[g][j] = lrelu(acc[g]);
    __syncthreads();
#pragma unroll
    for (int g = 0; g < 4; g++) acc[g] = bg2[j];
    for (int i = 0; i < 128; i++) {
        float w = Wg2[i * 128 + j];
#pragma unroll
        for (int g = 0; g < 4; g++) acc[g] += sh[g][i] * w;
    }
#pragma unroll
    for (int g = 0; g < 4; g++) sh2[g][j] = lrelu(acc[g]);
    __syncthreads();
    if (j < 32) {
        int g = j >> 3, e = j & 7;
        float lg = bg3[e];
        for (int i = 0; i < 128; i++) lg += sh2[g][i] * Wg3[i * 8 + e];
        slog[g][e] = lg;
    }
    __syncthreads();
    for (int e = 0; e < 8; e++) {
#pragma unroll
        for (int g = 0; g < 4; g++) acc[g] = Eb1[e * 128 + j];
        for (int i = 0; i < 144; i++) {
            float w = EW1[(e * 144 + i) * 128 + j];
#pragma unroll
            for (int g = 0; g < 4; g++) acc[g] += sx[g][i] * w;
        }
        __syncthreads();
#pragma unroll
        for (int g = 0; g < 4; g++) sh[g][j] = lrelu(acc[g]);
        __syncthreads();
#pragma unroll
        for (int g = 0; g < 4; g++) acc[g] = Eb2[e * 128 + j];
        for (int i = 0; i < 128; i++) {
            float w = EW2[(e * 128 + i) * 128 + j];
#pragma unroll
            for (int g = 0; g < 4; g++) acc[g] += sh[g][i] * w;
        }
        float w3 = EW3[e * 128 + j];
#pragma unroll
        for (int g = 0; g < 4; g++) {
            float t = lrelu(acc[g]) * w3;
#pragma unroll
            for (int o = 16; o > 0; o >>= 1) t += __shfl_xor_sync(0xffffffffu, t, o);
            if ((j & 31) == 0) red[g][j >> 5] = t;
        }
        __syncthreads();
        if (j < 4) sev[j][e] = red[j][0] + red[j][1] + red[j][2] + red[j][3] + Eb3[e];
        __syncthreads();
    }
    if (j < 4 && b0 + j < B) {
        float mx = -1e30f;
#pragma unroll
        for (int e = 0; e < 8; e++) mx = fmaxf(mx, slog[j][e]);
        float den = 0.f, num = 0.f;
#pragma unroll
        for (int e = 0; e < 8; e++) {
            float p = __expf(slog[j][e] - mx);
            den += p;
            num += p * sev[j][e];
        }
        out[b0 + j] = num / den;
    }
}

// ---------------- launch ----------------
extern "C" void kernel_launch(void* const* d_in, const int* in_sizes, int n_in,
                              void* d_out, int out_size) {
    const float* node_feat = (const float*)d_in[0];
    const float* edge_feat = (const float*)d_in[1];
    const int*   src = (const int*)d_in[2];
    const int*   dst = (const int*)d_in[3];
    const int*   rev = (const int*)d_in[4];
    const int*   gid = (const int*)d_in[5];
    const float* extra = (const float*)d_in[6];
    const float* W_edge = (const float*)d_in[7];
    const float* W_upd = (const float*)d_in[8];
    const float* W_node = (const float*)d_in[9];
    const float* b_node = (const float*)d_in[10];
    const float* Wg1 = (const float*)d_in[11];
    const float* bg1 = (const float*)d_in[12];
    const float* Wg2 = (const float*)d_in[13];
    const float* bg2 = (const float*)d_in[14];
    const float* Wg3 = (const float*)d_in[15];
    const float* bg3 = (const float*)d_in[16];
    const float* EW1 = (const float*)d_in[17];
    const float* Eb1 = (const float*)d_in[18];
    const float* EW2 = (const float*)d_in[19];
    const float* Eb2 = (const float*)d_in[20];
    const float* EW3 = (const float*)d_in[21];
    const float* Eb3 = (const float*)d_in[22];
    float* out = (float*)d_out;

    int N = in_sizes[0] / 64;
    int E = in_sizes[2];
    int B = in_sizes[6] / 16;

    float *pH0, *pPa, *pPb, *pSA, *pSB, *pMn, *pNW, *pGr;
    cudaGetSymbolAddress((void**)&pH0, g_h0);
    cudaGetSymbolAddress((void**)&pPa, g_Pa);
    cudaGetSymbolAddress((void**)&pPb, g_Pb);
    cudaGetSymbolAddress((void**)&pSA, g_SA);
    cudaGetSymbolAddress((void**)&pSB, g_SB);
    cudaGetSymbolAddress((void**)&pMn, g_mnode);
    cudaGetSymbolAddress((void**)&pNW, g_nodeW);
    cudaGetSymbolAddress((void**)&pGr, g_graph);

    const int SM0 = 27648 * 4 + 2 * TILE_E * 4;
    const int SMR = 24576 * 4 + 3 * TILE_E * 4;
    const int SMN = (192 * 128 + 16 * 192) * 4;
    cudaFuncSetAttribute(k_round0, cudaFuncAttributeMaxDynamicSharedMemorySize, SM0);
    cudaFuncSetAttribute(k_round, cudaFuncAttributeMaxDynamicSharedMemorySize, SMR);
    cudaFuncSetAttribute(k_node, cudaFuncAttributeMaxDynamicSharedMemorySize, SMN);

    int nd4 = N * 32;
    int zg = (nd4 + 255) / 256;
    int gg = (B * 32 + 255) / 256;

    // upfront zeros: SA, SB, mnode, graph
    k_zero<<<zg, 256>>>((float4*)pSA, nd4);
    k_zero<<<zg, 256>>>((float4*)pSB, nd4);
    k_zero<<<zg, 256>>>((float4*)pMn, nd4);
    k_zero<<<gg, 256>>>((float4*)pGr, B * 32);

    k_nodeW<<<(N + 15) / 16, 128>>>(node_feat, W_edge, pNW, N);

    // round 0: h0 -> Pa, SA
    k_round0<<<PERSIST, 256, SM0>>>(edge_feat, W_edge, W_upd, pNW, src, dst,
                                    pH0, pPa, pSA, E);
    // round 1: (SA,Pa) -> Pb, SB
    k_round<<<PERSIST, 256, SMR>>>(pSA, pPa, pH0, W_upd, src, dst, rev, pPb, pSB, E);
    // round 2: (SB,Pb) -> Pa, SA (re-zero SA)
    k_zero<<<zg, 256>>>((float4*)pSA, nd4);
    k_round<<<PERSIST, 256, SMR>>>(pSB, pPb, pH0, W_upd, src, dst, rev, pPa, pSA, E);
    // round 3: (SA,Pa) -> Pb, SB (re-zero SB)
    k_zero<<<zg, 256>>>((float4*)pSB, nd4);
    k_round<<<PERSIST, 256, SMR>>>(pSA, pPa, pH0, W_upd, src, dst, rev, pPb, pSB, E);

    // h4 -> m_node
    int fg = (E * 32 + 255) / 256;
    k_final<<<fg, 256>>>(pSB, pPb, pH0, src, dst, rev, pMn, E);

    // node MLP + readout
    k_node<<<PERSIST, 128, SMN>>>(node_feat, pMn, W_node, b_node, gid, pGr, N);

    // MoE head
    k_moe<<<(B + 3) / 4, 128>>>(pGr, extra, Wg1, bg1, Wg2, bg2, Wg3, bg3,
                                EW1, Eb1, EW2, Eb2, EW3, Eb3, out, B);
}

// round 15
// speedup vs baseline: 1.1300x; 1.1300x over previous
#include <cuda_runtime.h>
#include <math.h>

#define D 128
#define TILE_E 64
#define PERSIST 304

// ---------------- device scratch (no allocation allowed) ----------------
__device__ float g_h0[640000 * 128];
__device__ float g_Pa[640000 * 128];
__device__ float g_Pb[640000 * 128];
__device__ float g_SA[50048 * 128];
__device__ float g_SB[50048 * 128];
__device__ float g_mnode[50048 * 128];
__device__ float g_nodeW[50048 * 128];
__device__ float g_graph[256 * 128];

__device__ __forceinline__ float lrelu(float x) { return x >= 0.f ? x : 0.01f * x; }

__device__ __forceinline__ unsigned long long ffma2(unsigned long long a,
                                                    unsigned long long b,
                                                    unsigned long long c) {
    unsigned long long d;
    asm("fma.rn.f32x2 %0, %1, %2, %3;" : "=l"(d) : "l"(a), "l"(b), "l"(c));
    return d;
}
__device__ __forceinline__ unsigned long long dup2(float x) {
    unsigned long long d;
    asm("mov.b64 %0, {%1, %1};" : "=l"(d) : "f"(x));
    return d;
}
__device__ __forceinline__ void red_add_v4(float* p, float4 v) {
    asm volatile("red.global.add.v4.f32 [%0], {%1, %2, %3, %4};"
                 :: "l"(p), "f"(v.x), "f"(v.y), "f"(v.z), "f"(v.w) : "memory");
}

// 64x128 tile GEMM: As [64][128] row-major, Ws [128][128] row-major (k-major)
__device__ __forceinline__ void gemm_tile(const float* __restrict__ As,
                                          const float* __restrict__ Ws,
                                          unsigned long long acc[4][4],
                                          int tx, int ty) {
    const float4* As4 = (const float4*)As;
    const int r0 = ty * 4;
#pragma unroll 2
    for (int k = 0; k < D; k += 4) {
        float4 a0 = As4[(r0 + 0) * 32 + (k >> 2)];
        float4 a1 = As4[(r0 + 1) * 32 + (k >> 2)];
        float4 a2 = As4[(r0 + 2) * 32 + (k >> 2)];
        float4 a3 = As4[(r0 + 3) * 32 + (k >> 2)];
        float v0[4] = {a0.x, a0.y, a0.z, a0.w};
        float v1[4] = {a1.x, a1.y, a1.z, a1.w};
        float v2[4] = {a2.x, a2.y, a2.z, a2.w};
        float v3[4] = {a3.x, a3.y, a3.z, a3.w};
#pragma unroll
        for (int kk = 0; kk < 4; kk++) {
            ulonglong2 b0 = *(const ulonglong2*)(Ws + (k + kk) * D + tx * 4);
            ulonglong2 b1 = *(const ulonglong2*)(Ws + (k + kk) * D + 64 + tx * 4);
            unsigned long long d0 = dup2(v0[kk]);
            unsigned long long d1 = dup2(v1[kk]);
            unsigned long long d2 = dup2(v2[kk]);
            unsigned long long d3 = dup2(v3[kk]);
            acc[0][0] = ffma2(d0, b0.x, acc[0][0]); acc[0][1] = ffma2(d0, b0.y, acc[0][1]);
            acc[0][2] = ffma2(d0, b1.x, acc[0][2]); acc[0][3] = ffma2(d0, b1.y, acc[0][3]);
            acc[1][0] = ffma2(d1, b0.x, acc[1][0]); acc[1][1] = ffma2(d1, b0.y, acc[1][1]);
            acc[1][2] = ffma2(d1, b1.x, acc[1][2]); acc[1][3] = ffma2(d1, b1.y, acc[1][3]);
            acc[2][0] = ffma2(d2, b0.x, acc[2][0]); acc[2][1] = ffma2(d2, b0.y, acc[2][1]);
            acc[2][2] = ffma2(d2, b1.x, acc[2][2]); acc[2][3] = ffma2(d2, b1.y, acc[2][3]);
            acc[3][0] = ffma2(d3, b0.x, acc[3][0]); acc[3][1] = ffma2(d3, b0.y, acc[3][1]);
            acc[3][2] = ffma2(d3, b1.x, acc[3][2]); acc[3][3] = ffma2(d3, b1.y, acc[3][3]);
        }
    }
}

__device__ __forceinline__ void writeback_tile(float* __restrict__ Pnew,
                                               float* __restrict__ Snew,
                                               const int* __restrict__ sdst,
                                               unsigned long long acc[4][4],
                                               int e0, int E, int tx, int ty) {
    union U { unsigned long long u; float2 f; };
#pragma unroll
    for (int i = 0; i < 4; i++) {
        int el = ty * 4 + i;
        int e = e0 + el;
        if (e < E) {
            U u0, u1, u2, u3;
            u0.u = acc[i][0]; u1.u = acc[i][1]; u2.u = acc[i][2]; u3.u = acc[i][3];
            float4 w0 = make_float4(u0.f.x, u0.f.y, u1.f.x, u1.f.y);
            float4 w1 = make_float4(u2.f.x, u2.f.y, u3.f.x, u3.f.y);
            ((float4*)Pnew)[e * 32 + tx] = w0;
            ((float4*)Pnew)[e * 32 + 16 + tx] = w1;
            int dn = sdst[el];
            red_add_v4(Snew + dn * D + tx * 4, w0);
            red_add_v4(Snew + dn * D + 64 + tx * 4, w1);
        }
    }
}

// ---------------- zero ----------------
__global__ void k_zero(float4* p, int n4) {
    int i = blockIdx.x * blockDim.x + threadIdx.x;
    if (i < n4) p[i] = make_float4(0.f, 0.f, 0.f, 0.f);
}

// ---------------- nodeW = node_feat @ W_edge[0:64,:] ----------------
__global__ void k_nodeW(const float* __restrict__ nf, const float* __restrict__ We,
                        float* __restrict__ nodeW, int N) {
    __shared__ float s[16 * 64];
    int n0 = blockIdx.x * 16;
    int j = threadIdx.x;
    for (int f = j; f < 16 * 64; f += 128) {
        int r = f >> 6, i = f & 63;
        int n = n0 + r;
        s[f] = (n < N) ? nf[n * 64 + i] : 0.f;
    }
    __syncthreads();
    float acc[16];
#pragma unroll
    for (int r = 0; r < 16; r++) acc[r] = 0.f;
    for (int i = 0; i < 64; i++) {
        float w = We[i * D + j];
#pragma unroll
        for (int r = 0; r < 16; r++) acc[r] += s[r * 64 + i] * w;
    }
#pragma unroll
    for (int r = 0; r < 16; r++) {
        int n = n0 + r;
        if (n < N) nodeW[n * D + j] = acc[r];
    }
}

// ---------------- round 0: h0 build + P0 = h0@W + scatter S0 ----------------
__global__ void __launch_bounds__(256, 2) k_round0(
    const float* __restrict__ edge_feat, const float* __restrict__ We,
    const float* __restrict__ W_upd, const float* __restrict__ nodeW,
    const int* __restrict__ src, const int* __restrict__ dst,
    float* __restrict__ h0, float* __restrict__ Pnew, float* __restrict__ Snew, int E) {
    extern __shared__ float sm[];
    float* As  = sm;
    float* Ws  = sm + 8192;
    float* Web = sm + 24576;
    float* sef = sm + 26624;
    int* ssrc  = (int*)(sm + 27648);
    int* sdst  = ssrc + TILE_E;
    int tid = threadIdx.x;
    int tx = tid & 15, ty = tid >> 4;

    for (int i = tid; i < D * D; i += 256) Ws[i] = W_upd[i];
    for (int i = tid; i < 16 * D; i += 256) Web[i] = We[64 * D + i];

    int numTiles = (E + TILE_E - 1) / TILE_E;
    for (int t = blockIdx.x; t < numTiles; t += gridDim.x) {
        int e0 = t * TILE_E;
        __syncthreads();
        if (tid < TILE_E) {
            int e = e0 + tid;
            ssrc[tid] = (e < E) ? src[e] : 0;
            sdst[tid] = (e < E) ? dst[e] : 0;
        }
        for (int f = tid; f < TILE_E * 16; f += 256) {
            int e = e0 + (f >> 4);
            sef[f] = (e < E) ? edge_feat[e0 * 16 + f] : 0.f;
        }
        __syncthreads();
#pragma unroll
        for (int it = 0; it < 8; it++) {
            int flat = it * 256 + tid;
            int el = flat >> 5, k4 = flat & 31;
            int e = e0 + el;
            float4 v = make_float4(0.f, 0.f, 0.f, 0.f);
            if (e < E) {
                v = ((const float4*)nodeW)[ssrc[el] * 32 + k4];
#pragma unroll
                for (int i = 0; i < 16; i++) {
                    float f = sef[el * 16 + i];
                    float4 w = ((const float4*)Web)[i * 32 + k4];
                    v.x += f * w.x; v.y += f * w.y; v.z += f * w.z; v.w += f * w.w;
                }
                v.x = lrelu(v.x); v.y = lrelu(v.y); v.z = lrelu(v.z); v.w = lrelu(v.w);
                ((float4*)h0)[e * 32 + k4] = v;
            }
            ((float4*)As)[flat] = v;
        }
        __syncthreads();
        unsigned long long acc[4][4];
#pragma unroll
        for (int i = 0; i < 4; i++)
#pragma unroll
            for (int jj = 0; jj < 4; jj++) acc[i][jj] = 0ULL;
        gemm_tile(As, Ws, acc, tx, ty);
        writeback_tile(Pnew, Snew, sdst, acc, e0, E, tx, ty);
    }
}

// ---------------- rounds 1..3: build h on the fly, P=h@W, scatter S ----------------
__global__ void __launch_bounds__(256, 2) k_round(
    const float* __restrict__ Sprev, const float* __restrict__ Pprev,
    const float* __restrict__ h0, const float* __restrict__ W_upd,
    const int* __restrict__ src, const int* __restrict__ dst, const int* __restrict__ rev,
    float* __restrict__ Pnew, float* __restrict__ Snew, int E) {
    extern __shared__ float sm[];
    float* As = sm;
    float* Ws = sm + 8192;
    int* ssrc = (int*)(sm + 24576);
    int* sdst = ssrc + TILE_E;
    int* srev = sdst + TILE_E;
    int tid = threadIdx.x;
    int tx = tid & 15, ty = tid >> 4;

    for (int i = tid; i < D * D; i += 256) Ws[i] = W_upd[i];

    int numTiles = (E + TILE_E - 1) / TILE_E;
    for (int t = blockIdx.x; t < numTiles; t += gridDim.x) {
        int e0 = t * TILE_E;
        __syncthreads();
        if (tid < TILE_E) {
            int e = e0 + tid;
            ssrc[tid] = (e < E) ? src[e] : 0;
            sdst[tid] = (e < E) ? dst[e] : 0;
            srev[tid] = (e < E) ? rev[e] : 0;
        }
        __syncthreads();
#pragma unroll
        for (int it = 0; it < 8; it++) {
            int flat = it * 256 + tid;
            int el = flat >> 5, k4 = flat & 31;
            int e = e0 + el;
            float4 v = make_float4(0.f, 0.f, 0.f, 0.f);
            if (e < E) {
                float4 s4 = ((const float4*)Sprev)[ssrc[el] * 32 + k4];
                float4 p4 = ((const float4*)Pprev)[srev[el] * 32 + k4];
                float4 z4 = ((const float4*)h0)[e * 32 + k4];
                v.x = lrelu(s4.x - p4.x + z4.x);
                v.y = lrelu(s4.y - p4.y + z4.y);
                v.z = lrelu(s4.z - p4.z + z4.z);
                v.w = lrelu(s4.w - p4.w + z4.w);
            }
            ((float4*)As)[flat] = v;
        }
        __syncthreads();
        unsigned long long acc[4][4];
#pragma unroll
        for (int i = 0; i < 4; i++)
#pragma unroll
            for (int jj = 0; jj < 4; jj++) acc[i][jj] = 0ULL;
        gemm_tile(As, Ws, acc, tx, ty);
        writeback_tile(Pnew, Snew, sdst, acc, e0, E, tx, ty);
    }
}

// ---------------- final: h4 build + scatter to m_node ----------------
__global__ void k_final(const float* __restrict__ Sprev, const float* __restrict__ Pprev,
                        const float* __restrict__ h0,
                        const int* __restrict__ src, const int* __restrict__ dst,
                        const int* __restrict__ rev, float* __restrict__ mnode, int E) {
    int idx = blockIdx.x * blockDim.x + threadIdx.x;
    if (idx >= E * 32) return;
    int e = idx >> 5, k4 = idx & 31;
    int sn = src[e], re = rev[e], dn = dst[e];
    float4 s4 = ((const float4*)Sprev)[sn * 32 + k4];
    float4 p4 = ((const float4*)Pprev)[re * 32 + k4];
    float4 z4 = ((const float4*)h0)[e * 32 + k4];
    float4 v;
    v.x = lrelu(s4.x - p4.x + z4.x);
    v.y = lrelu(s4.y - p4.y + z4.y);
    v.z = lrelu(s4.z - p4.z + z4.z);
    v.w = lrelu(s4.w - p4.w + z4.w);
    red_add_v4(mnode + dn * D + k4 * 4, v);
}

// ---------------- node MLP + graph readout ----------------
__global__ void __launch_bounds__(128, 2) k_node(
    const float* __restrict__ nf, const float* __restrict__ mnode,
    const float* __restrict__ Wn, const float* __restrict__ bn,
    const int* __restrict__ gid, float* __restrict__ graph, int N) {
    extern __shared__ float sm[];
    float* Wns = sm;            // 192*128
    float* xc  = sm + 24576;    // 16*192
    int tid = threadIdx.x;
    for (int i = tid; i < 192 * 128; i += 128) Wns[i] = Wn[i];
    float bj = bn[tid];
    int numTiles = (N + 15) / 16;
    for (int t = blockIdx.x; t < numTiles; t += gridDim.x) {
        int n0 = t * 16;
        __syncthreads();
        for (int f = tid; f < 16 * 64; f += 128) {
            int r = f >> 6, i = f & 63; int n = n0 + r;
            xc[r * 192 + i] = (n < N) ? nf[n * 64 + i] : 0.f;
        }
        for (int f = tid; f < 16 * 128; f += 128) {
            int r = f >> 7, i = f & 127; int n = n0 + r;
            xc[r * 192 + 64 + i] = (n < N) ? mnode[n * 128 + i] : 0.f;
        }
        __syncthreads();
        for (int r = 0; r < 16; r++) {
            int n = n0 + r;
            if (n >= N) break;
            float acc = bj;
#pragma unroll 8
            for (int i = 0; i < 192; i++) acc += xc[r * 192 + i] * Wns[i * 128 + tid];
            atomicAdd(&graph[gid[n] * 128 + tid], lrelu(acc));
        }
    }
}

// ---------------- MoE head: 4 graphs per block ----------------
__global__ void k_moe(const float* __restrict__ graph, const float* __restrict__ extra,
                      const float* __restrict__ Wg1, const float* __restrict__ bg1,
                      const float* __restrict__ Wg2, const float* __restrict__ bg2,
                      const float* __restrict__ Wg3, const float* __restrict__ bg3,
                      const float* __restrict__ EW1, const float* __restrict__ Eb1,
                      const float* __restrict__ EW2, const float* __restrict__ Eb2,
                      const float* __restrict__ EW3, const float* __restrict__ Eb3,
                      float* __restrict__ out, int B) {
    __shared__ float sx[4][144];
    __shared__ float sh[4][128];
    __shared__ float sh2[4][128];
    __shared__ float slog[4][8];
    __shared__ float sev[4][8];
    __shared__ float red[4][4];
    int j = threadIdx.x;
    int b0 = blockIdx.x * 4;
    for (int g = 0; g < 4; g++) {
        int b = b0 + g;
        if (b < B) {
            sx[g][j] = graph[b * 128 + j];
            if (j < 16) sx[g][128 + j] = extra[b * 16 + j];
        } else {
            sx[g][j] = 0.f;
            if (j < 16) sx[g][128 + j] = 0.f;
        }
    }
    __syncthreads();
    float acc[4];
#pragma unroll
    for (int g = 0; g < 4; g++) acc[g] = bg1[j];
    for (int i = 0; i < 144; i++) {
        float w = Wg1[i * 128 + j];
#pragma unroll
        for (int g = 0; g < 4; g++) acc[g] += sx[g][i] * w;
    }
#pragma unroll
    for (int g = 0; g < 4; g++) sh[g][j] = lrelu(acc[g]);
    __syncthreads();
#pragma unroll
    for (int g = 0; g < 4; g++) acc[g] = bg2[j];
    for (int i = 0; i < 128; i++) {
        float w = Wg2[i * 128 + j];
#pragma unroll
        for (int g = 0; g < 4; g++) acc[g] += sh[g][i] * w;
    }
#pragma unroll
    for (int g = 0; g < 4; g++) sh2[g][j] = lrelu(acc[g]);
    __syncthreads();
    if (j < 32) {
        int g = j >> 3, e = j & 7;
        float lg = bg3[e];
        for (int i = 0; i < 128; i++) lg += sh2[g][i] * Wg3[i * 8 + e];
        slog[g][e] = lg;
    }
    __syncthreads();
    for (int e = 0; e < 8; e++) {
#pragma unroll
        for (int g = 0; g < 4; g++) acc[g] = Eb1[e * 128 + j];
        for (int i = 0; i < 144; i++) {
            float w = EW1[(e * 144 + i) * 128 + j];
#pragma unroll
            for (int g = 0; g < 4; g++) acc[g] += sx[g][i] * w;
        }
        __syncthreads();
#pragma unroll
        for (int g = 0; g < 4; g++) sh[g][j] = lrelu(acc[g]);
        __syncthreads();
#pragma unroll
        for (int g = 0; g < 4; g++) acc[g] = Eb2[e * 128 + j];
        for (int i = 0; i < 128; i++) {
            float w = EW2[(e * 128 + i) * 128 + j];
#pragma unroll
            for (int g = 0; g < 4; g++) acc[g] += sh[g][i] * w;
        }
        float w3 = EW3[e * 128 + j];
#pragma unroll
        for (int g = 0; g < 4; g++) {
            float t = lrelu(acc[g]) * w3;
#pragma unroll
            for (int o = 16; o > 0; o >>= 1) t += __shfl_xor_sync(0xffffffffu, t, o);
            if ((j & 31) == 0) red[g][j >> 5] = t;
        }
        __syncthreads();
        if (j < 4) sev[j][e] = red[j][0] + red[j][1] + red[j][2] + red[j][3] + Eb3[e];
        __syncthreads();
    }
    if (j < 4 && b0 + j < B) {
        float mx = -1e30f;
#pragma unroll
        for (int e = 0; e < 8; e++) mx = fmaxf(mx, slog[j][e]);
        float den = 0.f, num = 0.f;
#pragma unroll
        for (int e = 0; e < 8; e++) {
            float p = __expf(slog[j][e] - mx);
            den += p;
            num += p * sev[j][e];
        }
        out[b0 + j] = num / den;
    }
}

// ---------------- launch ----------------
extern "C" void kernel_launch(void* const* d_in, const int* in_sizes, int n_in,
                              void* d_out, int out_size) {
    const float* node_feat = (const float*)d_in[0];
    const float* edge_feat = (const float*)d_in[1];
    const int*   src = (const int*)d_in[2];
    const int*   dst = (const int*)d_in[3];
    const int*   rev = (const int*)d_in[4];
    const int*   gid = (const int*)d_in[5];
    const float* extra = (const float*)d_in[6];
    const float* W_edge = (const float*)d_in[7];
    const float* W_upd = (const float*)d_in[8];
    const float* W_node = (const float*)d_in[9];
    const float* b_node = (const float*)d_in[10];
    const float* Wg1 = (const float*)d_in[11];
    const float* bg1 = (const float*)d_in[12];
    const float* Wg2 = (const float*)d_in[13];
    const float* bg2 = (const float*)d_in[14];
    const float* Wg3 = (const float*)d_in[15];
    const float* bg3 = (const float*)d_in[16];
    const float* EW1 = (const float*)d_in[17];
    const float* Eb1 = (const float*)d_in[18];
    const float* EW2 = (const float*)d_in[19];
    const float* Eb2 = (const float*)d_in[20];
    const float* EW3 = (const float*)d_in[21];
    const float* Eb3 = (const float*)d_in[22];
    float* out = (float*)d_out;

    int N = in_sizes[0] / 64;
    int E = in_sizes[2];
    int B = in_sizes[6] / 16;

    float *pH0, *pPa, *pPb, *pSA, *pSB, *pMn, *pNW, *pGr;
    cudaGetSymbolAddress((void**)&pH0, g_h0);
    cudaGetSymbolAddress((void**)&pPa, g_Pa);
    cudaGetSymbolAddress((void**)&pPb, g_Pb);
    cudaGetSymbolAddress((void**)&pSA, g_SA);
    cudaGetSymbolAddress((void**)&pSB, g_SB);
    cudaGetSymbolAddress((void**)&pMn, g_mnode);
    cudaGetSymbolAddress((void**)&pNW, g_nodeW);
    cudaGetSymbolAddress((void**)&pGr, g_graph);

    const int SM0 = 27648 * 4 + 2 * TILE_E * 4;
    const int SMR = 24576 * 4 + 3 * TILE_E * 4;
    const int SMN = (192 * 128 + 16 * 192) * 4;
    cudaFuncSetAttribute(k_round0, cudaFuncAttributeMaxDynamicSharedMemorySize, SM0);
    cudaFuncSetAttribute(k_round, cudaFuncAttributeMaxDynamicSharedMemorySize, SMR);
    cudaFuncSetAttribute(k_node, cudaFuncAttributeMaxDynamicSharedMemorySize, SMN);

    int nd4 = N * 32;
    int zg = (nd4 + 255) / 256;
    int gg = (B * 32 + 255) / 256;

    // upfront zeros: SA, SB, mnode, graph
    k_zero<<<zg, 256>>>((float4*)pSA, nd4);
    k_zero<<<zg, 256>>>((float4*)pSB, nd4);
    k_zero<<<zg, 256>>>((float4*)pMn, nd4);
    k_zero<<<gg, 256>>>((float4*)pGr, B * 32);

    k_nodeW<<<(N + 15) / 16, 128>>>(node_feat, W_edge, pNW, N);

    // round 0: h0 -> Pa, SA
    k_round0<<<PERSIST, 256, SM0>>>(edge_feat, W_edge, W_upd, pNW, src, dst,
                                    pH0, pPa, pSA, E);
    // round 1: (SA,Pa) -> Pb, SB
    k_round<<<PERSIST, 256, SMR>>>(pSA, pPa, pH0, W_upd, src, dst, rev, pPb, pSB, E);
    // round 2: (SB,Pb) -> Pa, SA (re-zero SA)
    k_zero<<<zg, 256>>>((float4*)pSA, nd4);
    k_round<<<PERSIST, 256, SMR>>>(pSB, pPb, pH0, W_upd, src, dst, rev, pPa, pSA, E);
    // round 3: (SA,Pa) -> Pb, SB (re-zero SB)
    k_zero<<<zg, 256>>>((float4*)pSB, nd4);
    k_round<<<PERSIST, 256, SMR>>>(pSA, pPa, pH0, W_upd, src, dst, rev, pPb, pSB, E);

    // h4 -> m_node
    int fg = (E * 32 + 255) / 256;
    k_final<<<fg, 256>>>(pSB, pPb, pH0, src, dst, rev, pMn, E);

    // node MLP + readout
    k_node<<<PERSIST, 128, SMN>>>(node_feat, pMn, W_node, b_node, gid, pGr, N);

    // MoE head
    k_moe<<<(B + 3) / 4, 128>>>(pGr, extra, Wg1, bg1, Wg2, bg2, Wg3, bg3,
                                EW1, Eb1, EW2, Eb2, EW3, Eb3, out, B);
}

// round 16
// speedup vs baseline: 1.1484x; 1.0163x over previous
#include <cuda_runtime.h>
#include <math.h>

#define D 128
#define TILE_E 64
#define PERSIST 304

// ---------------- device scratch (no allocation allowed) ----------------
__device__ float g_h0[640000 * 128];
__device__ float g_Pa[640000 * 128];
__device__ float g_Pb[640000 * 128];
__device__ float g_SA[50048 * 128];
__device__ float g_SB[50048 * 128];
__device__ float g_mnode[50048 * 128];
__device__ float g_nodeW[50048 * 128];
__device__ float g_graph[256 * 128];

__device__ __forceinline__ float lrelu(float x) { return x >= 0.f ? x : 0.01f * x; }

__device__ __forceinline__ unsigned long long ffma2(unsigned long long a,
                                                    unsigned long long b,
                                                    unsigned long long c) {
    unsigned long long d;
    asm("fma.rn.f32x2 %0, %1, %2, %3;" : "=l"(d) : "l"(a), "l"(b), "l"(c));
    return d;
}
__device__ __forceinline__ unsigned long long dup2(float x) {
    unsigned long long d;
    asm("mov.b64 %0, {%1, %1};" : "=l"(d) : "f"(x));
    return d;
}
__device__ __forceinline__ void red_add_v4(float* p, float4 v) {
    asm volatile("red.global.add.v4.f32 [%0], {%1, %2, %3, %4};"
                 :: "l"(p), "f"(v.x), "f"(v.y), "f"(v.z), "f"(v.w) : "memory");
}

// 64x128 tile GEMM: As [64][128] row-major, Ws [128][128] row-major (k-major)
__device__ __forceinline__ void gemm_tile(const float* __restrict__ As,
                                          const float* __restrict__ Ws,
                                          unsigned long long acc[4][4],
                                          int tx, int ty) {
    const float4* As4 = (const float4*)As;
    const int r0 = ty * 4;
#pragma unroll 2
    for (int k = 0; k < D; k += 4) {
        float4 a0 = As4[(r0 + 0) * 32 + (k >> 2)];
        float4 a1 = As4[(r0 + 1) * 32 + (k >> 2)];
        float4 a2 = As4[(r0 + 2) * 32 + (k >> 2)];
        float4 a3 = As4[(r0 + 3) * 32 + (k >> 2)];
        float v0[4] = {a0.x, a0.y, a0.z, a0.w};
        float v1[4] = {a1.x, a1.y, a1.z, a1.w};
        float v2[4] = {a2.x, a2.y, a2.z, a2.w};
        float v3[4] = {a3.x, a3.y, a3.z, a3.w};
#pragma unroll
        for (int kk = 0; kk < 4; kk++) {
            ulonglong2 b0 = *(const ulonglong2*)(Ws + (k + kk) * D + tx * 4);
            ulonglong2 b1 = *(const ulonglong2*)(Ws + (k + kk) * D + 64 + tx * 4);
            unsigned long long d0 = dup2(v0[kk]);
            unsigned long long d1 = dup2(v1[kk]);
            unsigned long long d2 = dup2(v2[kk]);
            unsigned long long d3 = dup2(v3[kk]);
            acc[0][0] = ffma2(d0, b0.x, acc[0][0]); acc[0][1] = ffma2(d0, b0.y, acc[0][1]);
            acc[0][2] = ffma2(d0, b1.x, acc[0][2]); acc[0][3] = ffma2(d0, b1.y, acc[0][3]);
            acc[1][0] = ffma2(d1, b0.x, acc[1][0]); acc[1][1] = ffma2(d1, b0.y, acc[1][1]);
            acc[1][2] = ffma2(d1, b1.x, acc[1][2]); acc[1][3] = ffma2(d1, b1.y, acc[1][3]);
            acc[2][0] = ffma2(d2, b0.x, acc[2][0]); acc[2][1] = ffma2(d2, b0.y, acc[2][1]);
            acc[2][2] = ffma2(d2, b1.x, acc[2][2]); acc[2][3] = ffma2(d2, b1.y, acc[2][3]);
            acc[3][0] = ffma2(d3, b0.x, acc[3][0]); acc[3][1] = ffma2(d3, b0.y, acc[3][1]);
            acc[3][2] = ffma2(d3, b1.x, acc[3][2]); acc[3][3] = ffma2(d3, b1.y, acc[3][3]);
        }
    }
}

__device__ __forceinline__ void writeback_tile(float* __restrict__ Pnew,
                                               float* __restrict__ Snew,
                                               const int* __restrict__ sdst,
                                               unsigned long long acc[4][4],
                                               int e0, int E, int tx, int ty) {
    union U { unsigned long long u; float2 f; };
#pragma unroll
    for (int i = 0; i < 4; i++) {
        int el = ty * 4 + i;
        int e = e0 + el;
        if (e < E) {
            U u0, u1, u2, u3;
            u0.u = acc[i][0]; u1.u = acc[i][1]; u2.u = acc[i][2]; u3.u = acc[i][3];
            float4 w0 = make_float4(u0.f.x, u0.f.y, u1.f.x, u1.f.y);
            float4 w1 = make_float4(u2.f.x, u2.f.y, u3.f.x, u3.f.y);
            ((float4*)Pnew)[e * 32 + tx] = w0;
            ((float4*)Pnew)[e * 32 + 16 + tx] = w1;
            int dn = sdst[el];
            red_add_v4(Snew + dn * D + tx * 4, w0);
            red_add_v4(Snew + dn * D + 64 + tx * 4, w1);
        }
    }
}

// ---------------- zero ----------------
__global__ void k_zero(float4* p, int n4) {
    int i = blockIdx.x * blockDim.x + threadIdx.x;
    if (i < n4) p[i] = make_float4(0.f, 0.f, 0.f, 0.f);
}

// ---------------- nodeW = node_feat @ W_edge[0:64,:] ----------------
__global__ void k_nodeW(const float* __restrict__ nf, const float* __restrict__ We,
                        float* __restrict__ nodeW, int N) {
    __shared__ float s[16 * 64];
    int n0 = blockIdx.x * 16;
    int j = threadIdx.x;
    for (int f = j; f < 16 * 64; f += 128) {
        int r = f >> 6, i = f & 63;
        int n = n0 + r;
        s[f] = (n < N) ? nf[n * 64 + i] : 0.f;
    }
    __syncthreads();
    float acc[16];
#pragma unroll
    for (int r = 0; r < 16; r++) acc[r] = 0.f;
    for (int i = 0; i < 64; i++) {
        float w = We[i * D + j];
#pragma unroll
        for (int r = 0; r < 16; r++) acc[r] += s[r * 64 + i] * w;
    }
#pragma unroll
    for (int r = 0; r < 16; r++) {
        int n = n0 + r;
        if (n < N) nodeW[n * D + j] = acc[r];
    }
}

// ---------------- round 0: h0 build + P0 = h0@W + scatter S0 ----------------
__global__ void __launch_bounds__(256, 2) k_round0(
    const float* __restrict__ edge_feat, const float* __restrict__ We,
    const float* __restrict__ W_upd, const float* __restrict__ nodeW,
    const int* __restrict__ src, const int* __restrict__ dst,
    float* __restrict__ h0, float* __restrict__ Pnew, float* __restrict__ Snew, int E) {
    extern __shared__ float sm[];
    float* As  = sm;
    float* Ws  = sm + 8192;
    float* Web = sm + 24576;
    float* sef = sm + 26624;
    int* ssrc  = (int*)(sm + 27648);
    int* sdst  = ssrc + TILE_E;
    int tid = threadIdx.x;
    int tx = tid & 15, ty = tid >> 4;

    for (int i = tid; i < D * D; i += 256) Ws[i] = W_upd[i];
    for (int i = tid; i < 16 * D; i += 256) Web[i] = We[64 * D + i];

    int numTiles = (E + TILE_E - 1) / TILE_E;
    int t = blockIdx.x;
    int r_s = 0, r_d = 0;
    float4 r_ef = make_float4(0.f, 0.f, 0.f, 0.f);
    if (t < numTiles) {
        if (tid < TILE_E) {
            int e = t * TILE_E + tid;
            r_s = (e < E) ? src[e] : 0;
            r_d = (e < E) ? dst[e] : 0;
        }
        {
            int e = t * TILE_E + (tid >> 2);
            if (e < E) r_ef = ((const float4*)edge_feat)[(size_t)t * 256 + tid];
        }
    }
    for (; t < numTiles; t += gridDim.x) {
        int e0 = t * TILE_E;
        __syncthreads();
        if (tid < TILE_E) {
            ssrc[tid] = r_s;
            sdst[tid] = r_d;
        }
        ((float4*)sef)[tid] = r_ef;
        __syncthreads();
#pragma unroll
        for (int it = 0; it < 8; it++) {
            int flat = it * 256 + tid;
            int el = flat >> 5, k4 = flat & 31;
            int e = e0 + el;
            float4 v = make_float4(0.f, 0.f, 0.f, 0.f);
            if (e < E) {
                v = ((const float4*)nodeW)[ssrc[el] * 32 + k4];
#pragma unroll
                for (int i = 0; i < 16; i++) {
                    float f = sef[el * 16 + i];
                    float4 w = ((const float4*)Web)[i * 32 + k4];
                    v.x += f * w.x; v.y += f * w.y; v.z += f * w.z; v.w += f * w.w;
                }
                v.x = lrelu(v.x); v.y = lrelu(v.y); v.z = lrelu(v.z); v.w = lrelu(v.w);
                ((float4*)h0)[e * 32 + k4] = v;
            }
            ((float4*)As)[flat] = v;
        }
        __syncthreads();
        // prefetch next tile's indices + edge features (overlaps gemm)
        int tn = t + gridDim.x;
        if (tn < numTiles) {
            if (tid < TILE_E) {
                int e = tn * TILE_E + tid;
                r_s = (e < E) ? src[e] : 0;
                r_d = (e < E) ? dst[e] : 0;
            }
            int e = tn * TILE_E + (tid >> 2);
            r_ef = make_float4(0.f, 0.f, 0.f, 0.f);
            if (e < E) r_ef = ((const float4*)edge_feat)[(size_t)tn * 256 + tid];
        }
        unsigned long long acc[4][4];
#pragma unroll
        for (int i = 0; i < 4; i++)
#pragma unroll
            for (int jj = 0; jj < 4; jj++) acc[i][jj] = 0ULL;
        gemm_tile(As, Ws, acc, tx, ty);
        writeback_tile(Pnew, Snew, sdst, acc, e0, E, tx, ty);
    }
}

// ---------------- rounds 1..3: build h on the fly, P=h@W, scatter S ----------------
__global__ void __launch_bounds__(256, 2) k_round(
    const float* __restrict__ Sprev, const float* __restrict__ Pprev,
    const float* __restrict__ h0, const float* __restrict__ W_upd,
    const int* __restrict__ src, const int* __restrict__ dst, const int* __restrict__ rev,
    float* __restrict__ Pnew, float* __restrict__ Snew, int E) {
    extern __shared__ float sm[];
    float* As = sm;
    float* Ws = sm + 8192;
    int* ssrc = (int*)(sm + 24576);
    int* sdst = ssrc + TILE_E;
    int* srev = sdst + TILE_E;
    int tid = threadIdx.x;
    int tx = tid & 15, ty = tid >> 4;

    for (int i = tid; i < D * D; i += 256) Ws[i] = W_upd[i];

    int numTiles = (E + TILE_E - 1) / TILE_E;
    int t = blockIdx.x;
    int r_s = 0, r_d = 0, r_r = 0;
    if (t < numTiles && tid < TILE_E) {
        int e = t * TILE_E + tid;
        r_s = (e < E) ? src[e] : 0;
        r_d = (e < E) ? dst[e] : 0;
        r_r = (e < E) ? rev[e] : 0;
    }
    for (; t < numTiles; t += gridDim.x) {
        int e0 = t * TILE_E;
        __syncthreads();
        if (tid < TILE_E) {
            ssrc[tid] = r_s;
            sdst[tid] = r_d;
            srev[tid] = r_r;
        }
        __syncthreads();
#pragma unroll
        for (int it = 0; it < 8; it++) {
            int flat = it * 256 + tid;
            int el = flat >> 5, k4 = flat & 31;
            int e = e0 + el;
            float4 v = make_float4(0.f, 0.f, 0.f, 0.f);
            if (e < E) {
                float4 s4 = ((const float4*)Sprev)[ssrc[el] * 32 + k4];
                float4 p4 = ((const float4*)Pprev)[srev[el] * 32 + k4];
                float4 z4 = ((const float4*)h0)[e * 32 + k4];
                v.x = lrelu(s4.x - p4.x + z4.x);
                v.y = lrelu(s4.y - p4.y + z4.y);
                v.z = lrelu(s4.z - p4.z + z4.z);
                v.w = lrelu(s4.w - p4.w + z4.w);
            }
            ((float4*)As)[flat] = v;
        }
        __syncthreads();
        // prefetch next tile's indices (overlaps gemm)
        int tn = t + gridDim.x;
        if (tn < numTiles && tid < TILE_E) {
            int e = tn * TILE_E + tid;
            r_s = (e < E) ? src[e] : 0;
            r_d = (e < E) ? dst[e] : 0;
            r_r = (e < E) ? rev[e] : 0;
        }
        unsigned long long acc[4][4];
#pragma unroll
        for (int i = 0; i < 4; i++)
#pragma unroll
            for (int jj = 0; jj < 4; jj++) acc[i][jj] = 0ULL;
        gemm_tile(As, Ws, acc, tx, ty);
        writeback_tile(Pnew, Snew, sdst, acc, e0, E, tx, ty);
    }
}

// ---------------- final: h4 build + scatter to m_node ----------------
__global__ void k_final(const float* __restrict__ Sprev, const float* __restrict__ Pprev,
                        const float* __restrict__ h0,
                        const int* __restrict__ src, const int* __restrict__ dst,
                        const int* __restrict__ rev, float* __restrict__ mnode, int E) {
    int idx = blockIdx.x * blockDim.x + threadIdx.x;
    if (idx >= E * 32) return;
    int e = idx >> 5, k4 = idx & 31;
    int sn = src[e], re = rev[e], dn = dst[e];
    float4 s4 = ((const float4*)Sprev)[sn * 32 + k4];
    float4 p4 = ((const float4*)Pprev)[re * 32 + k4];
    float4 z4 = ((const float4*)h0)[e * 32 + k4];
    float4 v;
    v.x = lrelu(s4.x - p4.x + z4.x);
    v.y = lrelu(s4.y - p4.y + z4.y);
    v.z = lrelu(s4.z - p4.z + z4.z);
    v.w = lrelu(s4.w - p4.w + z4.w);
    red_add_v4(mnode + dn * D + k4 * 4, v);
}

// ---------------- node MLP + graph readout ----------------
__global__ void __launch_bounds__(128, 2) k_node(
    const float* __restrict__ nf, const float* __restrict__ mnode,
    const float* __restrict__ Wn, const float* __restrict__ bn,
    const int* __restrict__ gid, float* __restrict__ graph, int N) {
    extern __shared__ float sm[];
    float* Wns = sm;            // 192*128
    float* xc  = sm + 24576;    // 16*192
    int tid = threadIdx.x;
    for (int i = tid; i < 192 * 128; i += 128) Wns[i] = Wn[i];
    float bj = bn[tid];
    int numTiles = (N + 15) / 16;
    for (int t = blockIdx.x; t < numTiles; t += gridDim.x) {
        int n0 = t * 16;
        __syncthreads();
        for (int f = tid; f < 16 * 64; f += 128) {
            int r = f >> 6, i = f & 63; int n = n0 + r;
            xc[r * 192 + i] = (n < N) ? nf[n * 64 + i] : 0.f;
        }
        for (int f = tid; f < 16 * 128; f += 128) {
            int r = f >> 7, i = f & 127; int n = n0 + r;
            xc[r * 192 + 64 + i] = (n < N) ? mnode[n * 128 + i] : 0.f;
        }
        __syncthreads();
        for (int r = 0; r < 16; r++) {
            int n = n0 + r;
            if (n >= N) break;
            float acc = bj;
#pragma unroll 8
            for (int i = 0; i < 192; i++) acc += xc[r * 192 + i] * Wns[i * 128 + tid];
            atomicAdd(&graph[gid[n] * 128 + tid], lrelu(acc));
        }
    }
}

// ---------------- MoE head: 4 graphs per block ----------------
__global__ void k_moe(const float* __restrict__ graph, const float* __restrict__ extra,
                      const float* __restrict__ Wg1, const float* __restrict__ bg1,
                      const float* __restrict__ Wg2, const float* __restrict__ bg2,
                      const float* __restrict__ Wg3, const float* __restrict__ bg3,
                      const float* __restrict__ EW1, const float* __restrict__ Eb1,
                      const float* __restrict__ EW2, const float* __restrict__ Eb2,
                      const float* __restrict__ EW3, const float* __restrict__ Eb3,
                      float* __restrict__ out, int B) {
    __shared__ float sx[4][144];
    __shared__ float sh[4][128];
    __shared__ float sh2[4][128];
    __shared__ float slog[4][8];
    __shared__ float sev[4][8];
    __shared__ float red[4][4];
    int j = threadIdx.x;
    int b0 = blockIdx.x * 4;
    for (int g = 0; g < 4; g++) {
        int b = b0 + g;
        if (b < B) {
            sx[g][j] = graph[b * 128 + j];
            if (j < 16) sx[g][128 + j] = extra[b * 16 + j];
        } else {
            sx[g][j] = 0.f;
            if (j < 16) sx[g][128 + j] = 0.f;
        }
    }
    __syncthreads();
    float acc[4];
#pragma unroll
    for (int g = 0; g < 4; g++) acc[g] = bg1[j];
    for (int i = 0; i < 144; i++) {
        float w = Wg1[i * 128 + j];
#pragma unroll
        for (int g = 0; g < 4; g++) acc[g] += sx[g][i] * w;
    }
#pragma unroll
    for (int g = 0; g < 4; g++) sh[g][j] = lrelu(acc[g]);
    __syncthreads();
#pragma unroll
    for (int g = 0; g < 4; g++) acc[g] = bg2[j];
    for (int i = 0; i < 128; i++) {
        float w = Wg2[i * 128 + j];
#pragma unroll
        for (int g = 0; g < 4; g++) acc[g] += sh[g][i] * w;
    }
#pragma unroll
    for (int g = 0; g < 4; g++) sh2[g][j] = lrelu(acc[g]);
    __syncthreads();
    if (j < 32) {
        int g = j >> 3, e = j & 7;
        float lg = bg3[e];
        for (int i = 0; i < 128; i++) lg += sh2[g][i] * Wg3[i * 8 + e];
        slog[g][e] = lg;
    }
    __syncthreads();
    for (int e = 0; e < 8; e++) {
#pragma unroll
        for (int g = 0; g < 4; g++) acc[g] = Eb1[e * 128 + j];
        for (int i = 0; i < 144; i++) {
            float w = EW1[(e * 144 + i) * 128 + j];
#pragma unroll
            for (int g = 0; g < 4; g++) acc[g] += sx[g][i] * w;
        }
        __syncthreads();
#pragma unroll
        for (int g = 0; g < 4; g++) sh[g][j] = lrelu(acc[g]);
        __syncthreads();
#pragma unroll
        for (int g = 0; g < 4; g++) acc[g] = Eb2[e * 128 + j];
        for (int i = 0; i < 128; i++) {
            float w = EW2[(e * 128 + i) * 128 + j];
#pragma unroll
            for (int g = 0; g < 4; g++) acc[g] += sh[g][i] * w;
        }
        float w3 = EW3[e * 128 + j];
#pragma unroll
        for (int g = 0; g < 4; g++) {
            float t = lrelu(acc[g]) * w3;
#pragma unroll
            for (int o = 16; o > 0; o >>= 1) t += __shfl_xor_sync(0xffffffffu, t, o);
            if ((j & 31) == 0) red[g][j >> 5] = t;
        }
        __syncthreads();
        if (j < 4) sev[j][e] = red[j][0] + red[j][1] + red[j][2] + red[j][3] + Eb3[e];
        __syncthreads();
    }
    if (j < 4 && b0 + j < B) {
        float mx = -1e30f;
#pragma unroll
        for (int e = 0; e < 8; e++) mx = fmaxf(mx, slog[j][e]);
        float den = 0.f, num = 0.f;
#pragma unroll
        for (int e = 0; e < 8; e++) {
            float p = __expf(slog[j][e] - mx);
            den += p;
            num += p * sev[j][e];
        }
        out[b0 + j] = num / den;
    }
}

// ---------------- launch ----------------
extern "C" void kernel_launch(void* const* d_in, const int* in_sizes, int n_in,
                              void* d_out, int out_size) {
    const float* node_feat = (const float*)d_in[0];
    const float* edge_feat = (const float*)d_in[1];
    const int*   src = (const int*)d_in[2];
    const int*   dst = (const int*)d_in[3];
    const int*   rev = (const int*)d_in[4];
    const int*   gid = (const int*)d_in[5];
    const float* extra = (const float*)d_in[6];
    const float* W_edge = (const float*)d_in[7];
    const float* W_upd = (const float*)d_in[8];
    const float* W_node = (const float*)d_in[9];
    const float* b_node = (const float*)d_in[10];
    const float* Wg1 = (const float*)d_in[11];
    const float* bg1 = (const float*)d_in[12];
    const float* Wg2 = (const float*)d_in[13];
    const float* bg2 = (const float*)d_in[14];
    const float* Wg3 = (const float*)d_in[15];
    const float* bg3 = (const float*)d_in[16];
    const float* EW1 = (const float*)d_in[17];
    const float* Eb1 = (const float*)d_in[18];
    const float* EW2 = (const float*)d_in[19];
    const float* Eb2 = (const float*)d_in[20];
    const float* EW3 = (const float*)d_in[21];
    const float* Eb3 = (const float*)d_in[22];
    float* out = (float*)d_out;

    int N = in_sizes[0] / 64;
    int E = in_sizes[2];
    int B = in_sizes[6] / 16;

    float *pH0, *pPa, *pPb, *pSA, *pSB, *pMn, *pNW, *pGr;
    cudaGetSymbolAddress((void**)&pH0, g_h0);
    cudaGetSymbolAddress((void**)&pPa, g_Pa);
    cudaGetSymbolAddress((void**)&pPb, g_Pb);
    cudaGetSymbolAddress((void**)&pSA, g_SA);
    cudaGetSymbolAddress((void**)&pSB, g_SB);
    cudaGetSymbolAddress((void**)&pMn, g_mnode);
    cudaGetSymbolAddress((void**)&pNW, g_nodeW);
    cudaGetSymbolAddress((void**)&pGr, g_graph);

    const int SM0 = 27648 * 4 + 2 * TILE_E * 4;
    const int SMR = 24576 * 4 + 3 * TILE_E * 4;
    const int SMN = (192 * 128 + 16 * 192) * 4;
    cudaFuncSetAttribute(k_round0, cudaFuncAttributeMaxDynamicSharedMemorySize, SM0);
    cudaFuncSetAttribute(k_round, cudaFuncAttributeMaxDynamicSharedMemorySize, SMR);
    cudaFuncSetAttribute(k_node, cudaFuncAttributeMaxDynamicSharedMemorySize, SMN);

    int nd4 = N * 32;
    int zg = (nd4 + 255) / 256;
    int gg = (B * 32 + 255) / 256;

    // upfront zeros: SA, SB, mnode, graph
    k_zero<<<zg, 256>>>((float4*)pSA, nd4);
    k_zero<<<zg, 256>>>((float4*)pSB, nd4);
    k_zero<<<zg, 256>>>((float4*)pMn, nd4);
    k_zero<<<gg, 256>>>((float4*)pGr, B * 32);

    k_nodeW<<<(N + 15) / 16, 128>>>(node_feat, W_edge, pNW, N);

    // round 0: h0 -> Pa, SA
    k_round0<<<PERSIST, 256, SM0>>>(edge_feat, W_edge, W_upd, pNW, src, dst,
                                    pH0, pPa, pSA, E);
    // round 1: (SA,Pa) -> Pb, SB
    k_round<<<PERSIST, 256, SMR>>>(pSA, pPa, pH0, W_upd, src, dst, rev, pPb, pSB, E);
    // round 2: (SB,Pb) -> Pa, SA (re-zero SA)
    k_zero<<<zg, 256>>>((float4*)pSA, nd4);
    k_round<<<PERSIST, 256, SMR>>>(pSB, pPb, pH0, W_upd, src, dst, rev, pPa, pSA, E);
    // round 3: (SA,Pa) -> Pb, SB (re-zero SB)
    k_zero<<<zg, 256>>>((float4*)pSB, nd4);
    k_round<<<PERSIST, 256, SMR>>>(pSA, pPa, pH0, W_upd, src, dst, rev, pPb, pSB, E);

    // h4 -> m_node
    int fg = (E * 32 + 255) / 256;
    k_final<<<fg, 256>>>(pSB, pPb, pH0, src, dst, rev, pMn, E);

    // node MLP + readout
    k_node<<<PERSIST, 128, SMN>>>(node_feat, pMn, W_node, b_node, gid, pGr, N);

    // MoE head
    k_moe<<<(B + 3) / 4, 128>>>(pGr, extra, Wg1, bg1, Wg2, bg2, Wg3, bg3,
                                EW1, Eb1, EW2, Eb2, EW3, Eb3, out, B);
}

// round 17
// speedup vs baseline: 1.1761x; 1.0242x over previous
#include <cuda_runtime.h>
#include <cuda_fp16.h>
#include <math.h>

#define D 128
#define TILE_E 64
#define PERSIST 304

// ---------------- device scratch (no allocation allowed) ----------------
__device__ unsigned int g_h0h[640000 * 64];   // h0 as half2 pairs (64 x half2 per edge)
__device__ float g_Pa[640000 * 128];
__device__ float g_Pb[640000 * 128];
__device__ float g_SA[50048 * 128];
__device__ float g_SB[50048 * 128];
__device__ float g_mnode[50048 * 128];
__device__ float g_nodeW[50048 * 128];
__device__ float g_graph[256 * 128];

__device__ __forceinline__ float lrelu(float x) { return x >= 0.f ? x : 0.01f * x; }

__device__ __forceinline__ unsigned long long ffma2(unsigned long long a,
                                                    unsigned long long b,
                                                    unsigned long long c) {
    unsigned long long d;
    asm("fma.rn.f32x2 %0, %1, %2, %3;" : "=l"(d) : "l"(a), "l"(b), "l"(c));
    return d;
}
__device__ __forceinline__ unsigned long long dup2(float x) {
    unsigned long long d;
    asm("mov.b64 %0, {%1, %1};" : "=l"(d) : "f"(x));
    return d;
}
__device__ __forceinline__ void red_add_v4(float* p, float4 v) {
    asm volatile("red.global.add.v4.f32 [%0], {%1, %2, %3, %4};"
                 :: "l"(p), "f"(v.x), "f"(v.y), "f"(v.z), "f"(v.w) : "memory");
}
__device__ __forceinline__ uint2 pack_h4(float4 v) {
    __half2 a = __floats2half2_rn(v.x, v.y);
    __half2 b = __floats2half2_rn(v.z, v.w);
    return make_uint2(*(unsigned int*)&a, *(unsigned int*)&b);
}
__device__ __forceinline__ float4 unpack_h4(uint2 u) {
    __half2 a = *(__half2*)&u.x;
    __half2 b = *(__half2*)&u.y;
    float2 fa = __half22float2(a);
    float2 fb = __half22float2(b);
    return make_float4(fa.x, fa.y, fb.x, fb.y);
}

// 64x128 tile GEMM: As [64][128] row-major, Ws [128][128] row-major (k-major)
__device__ __forceinline__ void gemm_tile(const float* __restrict__ As,
                                          const float* __restrict__ Ws,
                                          unsigned long long acc[4][4],
                                          int tx, int ty) {
    const float4* As4 = (const float4*)As;
    const int r0 = ty * 4;
#pragma unroll 2
    for (int k = 0; k < D; k += 4) {
        float4 a0 = As4[(r0 + 0) * 32 + (k >> 2)];
        float4 a1 = As4[(r0 + 1) * 32 + (k >> 2)];
        float4 a2 = As4[(r0 + 2) * 32 + (k >> 2)];
        float4 a3 = As4[(r0 + 3) * 32 + (k >> 2)];
        float v0[4] = {a0.x, a0.y, a0.z, a0.w};
        float v1[4] = {a1.x, a1.y, a1.z, a1.w};
        float v2[4] = {a2.x, a2.y, a2.z, a2.w};
        float v3[4] = {a3.x, a3.y, a3.z, a3.w};
#pragma unroll
        for (int kk = 0; kk < 4; kk++) {
            ulonglong2 b0 = *(const ulonglong2*)(Ws + (k + kk) * D + tx * 4);
            ulonglong2 b1 = *(const ulonglong2*)(Ws + (k + kk) * D + 64 + tx * 4);
            unsigned long long d0 = dup2(v0[kk]);
            unsigned long long d1 = dup2(v1[kk]);
            unsigned long long d2 = dup2(v2[kk]);
            unsigned long long d3 = dup2(v3[kk]);
            acc[0][0] = ffma2(d0, b0.x, acc[0][0]); acc[0][1] = ffma2(d0, b0.y, acc[0][1]);
            acc[0][2] = ffma2(d0, b1.x, acc[0][2]); acc[0][3] = ffma2(d0, b1.y, acc[0][3]);
            acc[1][0] = ffma2(d1, b0.x, acc[1][0]); acc[1][1] = ffma2(d1, b0.y, acc[1][1]);
            acc[1][2] = ffma2(d1, b1.x, acc[1][2]); acc[1][3] = ffma2(d1, b1.y, acc[1][3]);
            acc[2][0] = ffma2(d2, b0.x, acc[2][0]); acc[2][1] = ffma2(d2, b0.y, acc[2][1]);
            acc[2][2] = ffma2(d2, b1.x, acc[2][2]); acc[2][3] = ffma2(d2, b1.y, acc[2][3]);
            acc[3][0] = ffma2(d3, b0.x, acc[3][0]); acc[3][1] = ffma2(d3, b0.y, acc[3][1]);
            acc[3][2] = ffma2(d3, b1.x, acc[3][2]); acc[3][3] = ffma2(d3, b1.y, acc[3][3]);
        }
    }
}

__device__ __forceinline__ void writeback_tile(float* __restrict__ Pnew,
                                               float* __restrict__ Snew,
                                               const int* __restrict__ sdst,
                                               unsigned long long acc[4][4],
                                               int e0, int E, int tx, int ty) {
    union U { unsigned long long u; float2 f; };
#pragma unroll
    for (int i = 0; i < 4; i++) {
        int el = ty * 4 + i;
        int e = e0 + el;
        if (e < E) {
            U u0, u1, u2, u3;
            u0.u = acc[i][0]; u1.u = acc[i][1]; u2.u = acc[i][2]; u3.u = acc[i][3];
            float4 w0 = make_float4(u0.f.x, u0.f.y, u1.f.x, u1.f.y);
            float4 w1 = make_float4(u2.f.x, u2.f.y, u3.f.x, u3.f.y);
            ((float4*)Pnew)[e * 32 + tx] = w0;
            ((float4*)Pnew)[e * 32 + 16 + tx] = w1;
            int dn = sdst[el];
            red_add_v4(Snew + dn * D + tx * 4, w0);
            red_add_v4(Snew + dn * D + 64 + tx * 4, w1);
        }
    }
}

// ---------------- zero ----------------
__global__ void k_zero(float4* p, int n4) {
    int i = blockIdx.x * blockDim.x + threadIdx.x;
    if (i < n4) p[i] = make_float4(0.f, 0.f, 0.f, 0.f);
}

// ---------------- nodeW = node_feat @ W_edge[0:64,:] ----------------
__global__ void k_nodeW(const float* __restrict__ nf, const float* __restrict__ We,
                        float* __restrict__ nodeW, int N) {
    __shared__ float s[16 * 64];
    int n0 = blockIdx.x * 16;
    int j = threadIdx.x;
    for (int f = j; f < 16 * 64; f += 128) {
        int r = f >> 6, i = f & 63;
        int n = n0 + r;
        s[f] = (n < N) ? nf[n * 64 + i] : 0.f;
    }
    __syncthreads();
    float acc[16];
#pragma unroll
    for (int r = 0; r < 16; r++) acc[r] = 0.f;
    for (int i = 0; i < 64; i++) {
        float w = We[i * D + j];
#pragma unroll
        for (int r = 0; r < 16; r++) acc[r] += s[r * 64 + i] * w;
    }
#pragma unroll
    for (int r = 0; r < 16; r++) {
        int n = n0 + r;
        if (n < N) nodeW[n * D + j] = acc[r];
    }
}

// ---------------- round 0: h0 build + P0 = h0@W + scatter S0 ----------------
__global__ void __launch_bounds__(256, 2) k_round0(
    const float* __restrict__ edge_feat, const float* __restrict__ We,
    const float* __restrict__ W_upd, const float* __restrict__ nodeW,
    const int* __restrict__ src, const int* __restrict__ dst,
    unsigned int* __restrict__ h0h, float* __restrict__ Pnew, float* __restrict__ Snew, int E) {
    extern __shared__ float sm[];
    float* As  = sm;
    float* Ws  = sm + 8192;
    float* Web = sm + 24576;
    float* sef = sm + 26624;
    int* ssrc  = (int*)(sm + 27648);
    int* sdst  = ssrc + TILE_E;
    int tid = threadIdx.x;
    int tx = tid & 15, ty = tid >> 4;

    for (int i = tid; i < D * D; i += 256) Ws[i] = W_upd[i];
    for (int i = tid; i < 16 * D; i += 256) Web[i] = We[64 * D + i];

    int numTiles = (E + TILE_E - 1) / TILE_E;
    int t = blockIdx.x;
    int r_s = 0, r_d = 0;
    float4 r_ef = make_float4(0.f, 0.f, 0.f, 0.f);
    if (t < numTiles) {
        if (tid < TILE_E) {
            int e = t * TILE_E + tid;
            r_s = (e < E) ? src[e] : 0;
            r_d = (e < E) ? dst[e] : 0;
        }
        {
            int e = t * TILE_E + (tid >> 2);
            if (e < E) r_ef = ((const float4*)edge_feat)[(size_t)t * 256 + tid];
        }
    }
    for (; t < numTiles; t += gridDim.x) {
        int e0 = t * TILE_E;
        __syncthreads();
        if (tid < TILE_E) {
            ssrc[tid] = r_s;
            sdst[tid] = r_d;
        }
        ((float4*)sef)[tid] = r_ef;
        __syncthreads();
#pragma unroll
        for (int it = 0; it < 8; it++) {
            int flat = it * 256 + tid;
            int el = flat >> 5, k4 = flat & 31;
            int e = e0 + el;
            float4 v = make_float4(0.f, 0.f, 0.f, 0.f);
            if (e < E) {
                v = ((const float4*)nodeW)[ssrc[el] * 32 + k4];
#pragma unroll
                for (int i = 0; i < 16; i++) {
                    float f = sef[el * 16 + i];
                    float4 w = ((const float4*)Web)[i * 32 + k4];
                    v.x += f * w.x; v.y += f * w.y; v.z += f * w.z; v.w += f * w.w;
                }
                v.x = lrelu(v.x); v.y = lrelu(v.y); v.z = lrelu(v.z); v.w = lrelu(v.w);
                ((uint2*)h0h)[e * 32 + k4] = pack_h4(v);
            }
            ((float4*)As)[flat] = v;
        }
        __syncthreads();
        // prefetch next tile's indices + edge features (overlaps gemm)
        int tn = t + gridDim.x;
        if (tn < numTiles) {
            if (tid < TILE_E) {
                int e = tn * TILE_E + tid;
                r_s = (e < E) ? src[e] : 0;
                r_d = (e < E) ? dst[e] : 0;
            }
            int e = tn * TILE_E + (tid >> 2);
            r_ef = make_float4(0.f, 0.f, 0.f, 0.f);
            if (e < E) r_ef = ((const float4*)edge_feat)[(size_t)tn * 256 + tid];
        }
        unsigned long long acc[4][4];
#pragma unroll
        for (int i = 0; i < 4; i++)
#pragma unroll
            for (int jj = 0; jj < 4; jj++) acc[i][jj] = 0ULL;
        gemm_tile(As, Ws, acc, tx, ty);
        writeback_tile(Pnew, Snew, sdst, acc, e0, E, tx, ty);
    }
}

// ---------------- rounds 1..3: build h on the fly, P=h@W, scatter S ----------------
__global__ void __launch_bounds__(256, 2) k_round(
    const float* __restrict__ Sprev, const float* __restrict__ Pprev,
    const unsigned int* __restrict__ h0h, const float* __restrict__ W_upd,
    const int* __restrict__ src, const int* __restrict__ dst, const int* __restrict__ rev,
    float* __restrict__ Pnew, float* __restrict__ Snew, int E) {
    extern __shared__ float sm[];
    float* As = sm;
    float* Ws = sm + 8192;
    int* ssrc = (int*)(sm + 24576);
    int* sdst = ssrc + TILE_E;
    int* srev = sdst + TILE_E;
    int tid = threadIdx.x;
    int tx = tid & 15, ty = tid >> 4;

    for (int i = tid; i < D * D; i += 256) Ws[i] = W_upd[i];

    int numTiles = (E + TILE_E - 1) / TILE_E;
    int t = blockIdx.x;
    int r_s = 0, r_d = 0, r_r = 0;
    if (t < numTiles && tid < TILE_E) {
        int e = t * TILE_E + tid;
        r_s = (e < E) ? src[e] : 0;
        r_d = (e < E) ? dst[e] : 0;
        r_r = (e < E) ? rev[e] : 0;
    }
    for (; t < numTiles; t += gridDim.x) {
        int e0 = t * TILE_E;
        __syncthreads();
        if (tid < TILE_E) {
            ssrc[tid] = r_s;
            sdst[tid] = r_d;
            srev[tid] = r_r;
        }
        __syncthreads();
#pragma unroll
        for (int it = 0; it < 8; it++) {
            int flat = it * 256 + tid;
            int el = flat >> 5, k4 = flat & 31;
            int e = e0 + el;
            float4 v = make_float4(0.f, 0.f, 0.f, 0.f);
            if (e < E) {
                float4 s4 = ((const float4*)Sprev)[ssrc[el] * 32 + k4];
                float4 p4 = ((const float4*)Pprev)[srev[el] * 32 + k4];
                float4 z4 = unpack_h4(((const uint2*)h0h)[e * 32 + k4]);
                v.x = lrelu(s4.x - p4.x + z4.x);
                v.y = lrelu(s4.y - p4.y + z4.y);
                v.z = lrelu(s4.z - p4.z + z4.z);
                v.w = lrelu(s4.w - p4.w + z4.w);
            }
            ((float4*)As)[flat] = v;
        }
        __syncthreads();
        // prefetch next tile's indices (overlaps gemm)
        int tn = t + gridDim.x;
        if (tn < numTiles && tid < TILE_E) {
            int e = tn * TILE_E + tid;
            r_s = (e < E) ? src[e] : 0;
            r_d = (e < E) ? dst[e] : 0;
            r_r = (e < E) ? rev[e] : 0;
        }
        unsigned long long acc[4][4];
#pragma unroll
        for (int i = 0; i < 4; i++)
#pragma unroll
            for (int jj = 0; jj < 4; jj++) acc[i][jj] = 0ULL;
        gemm_tile(As, Ws, acc, tx, ty);
        writeback_tile(Pnew, Snew, sdst, acc, e0, E, tx, ty);
    }
}

// ---------------- final: h4 build + scatter to m_node ----------------
__global__ void k_final(const float* __restrict__ Sprev, const float* __restrict__ Pprev,
                        const unsigned int* __restrict__ h0h,
                        const int* __restrict__ src, const int* __restrict__ dst,
                        const int* __restrict__ rev, float* __restrict__ mnode, int E) {
    int idx = blockIdx.x * blockDim.x + threadIdx.x;
    if (idx >= E * 32) return;
    int e = idx >> 5, k4 = idx & 31;
    int sn = src[e], re = rev[e], dn = dst[e];
    float4 s4 = ((const float4*)Sprev)[sn * 32 + k4];
    float4 p4 = ((const float4*)Pprev)[re * 32 + k4];
    float4 z4 = unpack_h4(((const uint2*)h0h)[e * 32 + k4]);
    float4 v;
    v.x = lrelu(s4.x - p4.x + z4.x);
    v.y = lrelu(s4.y - p4.y + z4.y);
    v.z = lrelu(s4.z - p4.z + z4.z);
    v.w = lrelu(s4.w - p4.w + z4.w);
    red_add_v4(mnode + dn * D + k4 * 4, v);
}

// ---------------- node MLP + graph readout ----------------
__global__ void __launch_bounds__(128, 2) k_node(
    const float* __restrict__ nf, const float* __restrict__ mnode,
    const float* __restrict__ Wn, const float* __restrict__ bn,
    const int* __restrict__ gid, float* __restrict__ graph, int N) {
    extern __shared__ float sm[];
    float* Wns = sm;            // 192*128
    float* xc  = sm + 24576;    // 16*192
    int tid = threadIdx.x;
    for (int i = tid; i < 192 * 128; i += 128) Wns[i] = Wn[i];
    float bj = bn[tid];
    int numTiles = (N + 15) / 16;
    for (int t = blockIdx.x; t < numTiles; t += gridDim.x) {
        int n0 = t * 16;
        __syncthreads();
        for (int f = tid; f < 16 * 64; f += 128) {
            int r = f >> 6, i = f & 63; int n = n0 + r;
            xc[r * 192 + i] = (n < N) ? nf[n * 64 + i] : 0.f;
        }
        for (int f = tid; f < 16 * 128; f += 128) {
            int r = f >> 7, i = f & 127; int n = n0 + r;
            xc[r * 192 + 64 + i] = (n < N) ? mnode[n * 128 + i] : 0.f;
        }
        __syncthreads();
        for (int r = 0; r < 16; r++) {
            int n = n0 + r;
            if (n >= N) break;
            float acc = bj;
#pragma unroll 8
            for (int i = 0; i < 192; i++) acc += xc[r * 192 + i] * Wns[i * 128 + tid];
            atomicAdd(&graph[gid[n] * 128 + tid], lrelu(acc));
        }
    }
}

// ---------------- MoE head: 4 graphs per block ----------------
__global__ void k_moe(const float* __restrict__ graph, const float* __restrict__ extra,
                      const float* __restrict__ Wg1, const float* __restrict__ bg1,
                      const float* __restrict__ Wg2, const float* __restrict__ bg2,
                      const float* __restrict__ Wg3, const float* __restrict__ bg3,
                      const float* __restrict__ EW1, const float* __restrict__ Eb1,
                      const float* __restrict__ EW2, const float* __restrict__ Eb2,
                      const float* __restrict__ EW3, const float* __restrict__ Eb3,
                      float* __restrict__ out, int B) {
    __shared__ float sx[4][144];
    __shared__ float sh[4][128];
    __shared__ float sh2[4][128];
    __shared__ float slog[4][8];
    __shared__ float sev[4][8];
    __shared__ float red[4][4];
    int j = threadIdx.x;
    int b0 = blockIdx.x * 4;
    for (int g = 0; g < 4; g++) {
        int b = b0 + g;
        if (b < B) {
            sx[g][j] = graph[b * 128 + j];
            if (j < 16) sx[g][128 + j] = extra[b * 16 + j];
        } else {
            sx[g][j] = 0.f;
            if (j < 16) sx[g][128 + j] = 0.f;
        }
    }
    __syncthreads();
    float acc[4];
#pragma unroll
    for (int g = 0; g < 4; g++) acc[g] = bg1[j];
    for (int i = 0; i < 144; i++) {
        float w = Wg1[i * 128 + j];
#pragma unroll
        for (int g = 0; g < 4; g++) acc[g] += sx[g][i] * w;
    }
#pragma unroll
    for (int g = 0; g < 4; g++) sh[g][j] = lrelu(acc[g]);
    __syncthreads();
#pragma unroll
    for (int g = 0; g < 4; g++) acc[g] = bg2[j];
    for (int i = 0; i < 128; i++) {
        float w = Wg2[i * 128 + j];
#pragma unroll
        for (int g = 0; g < 4; g++) acc[g] += sh[g][i] * w;
    }
#pragma unroll
    for (int g = 0; g < 4; g++) sh2[g][j] = lrelu(acc[g]);
    __syncthreads();
    if (j < 32) {
        int g = j >> 3, e = j & 7;
        float lg = bg3[e];
        for (int i = 0; i < 128; i++) lg += sh2[g][i] * Wg3[i * 8 + e];
        slog[g][e] = lg;
    }
    __syncthreads();
    for (int e = 0; e < 8; e++) {
#pragma unroll
        for (int g = 0; g < 4; g++) acc[g] = Eb1[e * 128 + j];
        for (int i = 0; i < 144; i++) {
            float w = EW1[(e * 144 + i) * 128 + j];
#pragma unroll
            for (int g = 0; g < 4; g++) acc[g] += sx[g][i] * w;
        }
        __syncthreads();
#pragma unroll
        for (int g = 0; g < 4; g++) sh[g][j] = lrelu(acc[g]);
        __syncthreads();
#pragma unroll
        for (int g = 0; g < 4; g++) acc[g] = Eb2[e * 128 + j];
        for (int i = 0; i < 128; i++) {
            float w = EW2[(e * 128 + i) * 128 + j];
#pragma unroll
            for (int g = 0; g < 4; g++) acc[g] += sh[g][i] * w;
        }
        float w3 = EW3[e * 128 + j];
#pragma unroll
        for (int g = 0; g < 4; g++) {
            float t = lrelu(acc[g]) * w3;
#pragma unroll
            for (int o = 16; o > 0; o >>= 1) t += __shfl_xor_sync(0xffffffffu, t, o);
            if ((j & 31) == 0) red[g][j >> 5] = t;
        }
        __syncthreads();
        if (j < 4) sev[j][e] = red[j][0] + red[j][1] + red[j][2] + red[j][3] + Eb3[e];
        __syncthreads();
    }
    if (j < 4 && b0 + j < B) {
        float mx = -1e30f;
#pragma unroll
        for (int e = 0; e < 8; e++) mx = fmaxf(mx, slog[j][e]);
        float den = 0.f, num = 0.f;
#pragma unroll
        for (int e = 0; e < 8; e++) {
            float p = __expf(slog[j][e] - mx);
            den += p;
            num += p * sev[j][e];
        }
        out[b0 + j] = num / den;
    }
}

// ---------------- launch ----------------
extern "C" void kernel_launch(void* const* d_in, const int* in_sizes, int n_in,
                              void* d_out, int out_size) {
    const float* node_feat = (const float*)d_in[0];
    const float* edge_feat = (const float*)d_in[1];
    const int*   src = (const int*)d_in[2];
    const int*   dst = (const int*)d_in[3];
    const int*   rev = (const int*)d_in[4];
    const int*   gid = (const int*)d_in[5];
    const float* extra = (const float*)d_in[6];
    const float* W_edge = (const float*)d_in[7];
    const float* W_upd = (const float*)d_in[8];
    const float* W_node = (const float*)d_in[9];
    const float* b_node = (const float*)d_in[10];
    const float* Wg1 = (const float*)d_in[11];
    const float* bg1 = (const float*)d_in[12];
    const float* Wg2 = (const float*)d_in[13];
    const float* bg2 = (const float*)d_in[14];
    const float* Wg3 = (const float*)d_in[15];
    const float* bg3 = (const float*)d_in[16];
    const float* EW1 = (const float*)d_in[17];
    const float* Eb1 = (const float*)d_in[18];
    const float* EW2 = (const float*)d_in[19];
    const float* Eb2 = (const float*)d_in[20];
    const float* EW3 = (const float*)d_in[21];
    const float* Eb3 = (const float*)d_in[22];
    float* out = (float*)d_out;

    int N = in_sizes[0] / 64;
    int E = in_sizes[2];
    int B = in_sizes[6] / 16;

    unsigned int* pH0;
    float *pPa, *pPb, *pSA, *pSB, *pMn, *pNW, *pGr;
    cudaGetSymbolAddress((void**)&pH0, g_h0h);
    cudaGetSymbolAddress((void**)&pPa, g_Pa);
    cudaGetSymbolAddress((void**)&pPb, g_Pb);
    cudaGetSymbolAddress((void**)&pSA, g_SA);
    cudaGetSymbolAddress((void**)&pSB, g_SB);
    cudaGetSymbolAddress((void**)&pMn, g_mnode);
    cudaGetSymbolAddress((void**)&pNW, g_nodeW);
    cudaGetSymbolAddress((void**)&pGr, g_graph);

    const int SM0 = 27648 * 4 + 2 * TILE_E * 4;
    const int SMR = 24576 * 4 + 3 * TILE_E * 4;
    const int SMN = (192 * 128 + 16 * 192) * 4;
    cudaFuncSetAttribute(k_round0, cudaFuncAttributeMaxDynamicSharedMemorySize, SM0);
    cudaFuncSetAttribute(k_round, cudaFuncAttributeMaxDynamicSharedMemorySize, SMR);
    cudaFuncSetAttribute(k_node, cudaFuncAttributeMaxDynamicSharedMemorySize, SMN);

    int nd4 = N * 32;
    int zg = (nd4 + 255) / 256;
    int gg = (B * 32 + 255) / 256;

    // upfront zeros: SA, SB, mnode, graph
    k_zero<<<zg, 256>>>((float4*)pSA, nd4);
    k_zero<<<zg, 256>>>((float4*)pSB, nd4);
    k_zero<<<zg, 256>>>((float4*)pMn, nd4);
    k_zero<<<gg, 256>>>((float4*)pGr, B * 32);

    k_nodeW<<<(N + 15) / 16, 128>>>(node_feat, W_edge, pNW, N);

    // round 0: h0 -> Pa, SA
    k_round0<<<PERSIST, 256, SM0>>>(edge_feat, W_edge, W_upd, pNW, src, dst,
                                    pH0, pPa, pSA, E);
    // round 1: (SA,Pa) -> Pb, SB
    k_round<<<PERSIST, 256, SMR>>>(pSA, pPa, pH0, W_upd, src, dst, rev, pPb, pSB, E);
    // round 2: (SB,Pb) -> Pa, SA (re-zero SA)
    k_zero<<<zg, 256>>>((float4*)pSA, nd4);
    k_round<<<PERSIST, 256, SMR>>>(pSB, pPb, pH0, W_upd, src, dst, rev, pPa, pSA, E);
    // round 3: (SA,Pa) -> Pb, SB (re-zero SB)
    k_zero<<<zg, 256>>>((float4*)pSB, nd4);
    k_round<<<PERSIST, 256, SMR>>>(pSA, pPa, pH0, W_upd, src, dst, rev, pPb, pSB, E);

    // h4 -> m_node
    int fg = (E * 32 + 255) / 256;
    k_final<<<fg, 256>>>(pSB, pPb, pH0, src, dst, rev, pMn, E);

    // node MLP + readout
    k_node<<<PERSIST, 128, SMN>>>(node_feat, pMn, W_node, b_node, gid, pGr, N);

    // MoE head
    k_moe<<<(B + 3) / 4, 128>>>(pGr, extra, Wg1, bg1, Wg2, bg2, Wg3, bg3,
                                EW1, Eb1, EW2, Eb2, EW3, Eb3, out, B);
}